// round 14
// baseline (speedup 1.0000x reference)
#include <cuda_runtime.h>
#include <cuda_fp16.h>
#include <cstdint>

#define NS   16384
#define DD   128
#define KK   10000
#define KT   128
#define NT2  79             // k-tiles; 79*128 = 10112
#define KPAD (NT2 * KT)
#define TM   128
#define GRID 148
#define NSLOT 4             // max CTAs covering one sample tile

// ---- vq_main smem layout (hi split only) ----
#define OFF_A  0            // 32768: x-tile hi split, swizzled fp16
#define OFF_B  32768        // 2 x 32768 buffers
#define BUFB   32768
#define OFF_H  98304        // 2 x 512
#define SMEM_TOTAL (OFF_H + 1024)

// ---- fallback2 smem layout (hi+mid A, double-buffered B) ----
#define F2_OFF_A 0          // 2 x 32768 (hi, mid)
#define F2_OFF_B 65536      // 2 x 65536 (hi|mid per buffer)
#define F2_BUFB  65536
#define F2_OFF_H 196608     // 2 x 512
#define F2_OFF_S 197632     // 128 ints (sample ids)
#define F2_OFF_R 198144     // 4096: reduction scratch
#define F2_SMEM  (F2_OFF_R + 4096)

__device__ uint4 g_B4[(size_t)NT2 * 4096];               // hi+mid swizzled B tiles
__device__ __align__(16) float g_cmT[(size_t)KPAD * DD]; // transposed means [k][d]
__device__ __align__(16) float g_h[KPAD];                // 0.5*||m||^2 (pad -> -3e38)
__device__ __align__(16) float4 g_top2[NS * NSLOT];      // per (sample, slot): b1,b2,i1
__device__ unsigned g_maxHb = 0;                         // max_k ||h_b|| (float bits)
__device__ unsigned g_maxRb = 0;                         // max_k ||r_b||
__device__ int g_fcount;
__device__ int g_flist[NS];
__device__ unsigned long long g_bestu64[NS];
__device__ int   g_idx[NS];
__device__ float g_partial[1024];
__device__ unsigned g_done;

// ---------------------------------------------------------------------------
__device__ __forceinline__ uint32_t smem_u32(const void* p) {
    uint32_t a;
    asm("{ .reg .u64 t; cvta.to.shared.u64 t, %1; cvt.u32.u64 %0, t; }"
        : "=r"(a) : "l"(p));
    return a;
}
__device__ __forceinline__ void cp16(uint32_t daddr, const void* src) {
    asm volatile("cp.async.cg.shared.global [%0], [%1], 16;"
                 :: "r"(daddr), "l"(src) : "memory");
}
#define CP_COMMIT() asm volatile("cp.async.commit_group;" ::: "memory")

#define LDSM4(R, addr)                                                        \
    asm volatile("ldmatrix.sync.aligned.m8n8.x4.shared.b16 {%0,%1,%2,%3}, [%4];" \
                 : "=r"((R)[0]), "=r"((R)[1]), "=r"((R)[2]), "=r"((R)[3])     \
                 : "r"(addr))

#define MMA(D, A, B0, B1)                                                     \
    asm volatile("mma.sync.aligned.m16n8k16.row.col.f32.f16.f16.f32 "         \
                 "{%0,%1,%2,%3}, {%4,%5,%6,%7}, {%8,%9}, {%0,%1,%2,%3};"      \
                 : "+f"((D)[0]), "+f"((D)[1]), "+f"((D)[2]), "+f"((D)[3])     \
                 : "r"((A)[0]), "r"((A)[1]), "r"((A)[2]), "r"((A)[3]),        \
                   "r"(B0), "r"(B1))

__device__ __forceinline__ unsigned pk2h(float a, float b) {
    __half2 t = __floats2half2_rn(a, b);
    return *reinterpret_cast<unsigned*>(&t);
}
__device__ __forceinline__ unsigned enc_f(float f) {
    unsigned s = __float_as_uint(f);
    return (s & 0x80000000u) ? ~s : (s | 0x80000000u);
}
// partition for GRID=148: 48 CTAs of 69 units, 100 of 68
__device__ __forceinline__ int cta_of(int u) {
    return (u < 48 * 69) ? (u / 69) : (48 + (u - 48 * 69) / 68);
}

// ---------------------------------------------------------------------------
// prep: transpose cm per 32-cluster sub-tile; (hi, mid) fp16 B image; cmT;
// h_k; per-k norm maxes; zero g_top2 / g_fcount / g_done. grid = 316 x 256.
// ---------------------------------------------------------------------------
__global__ void prepB_kernel(const float* __restrict__ cm) {
    __shared__ float st[32][132];
    const int t = blockIdx.x >> 2;
    const int sub = blockIdx.x & 3;
    const int kbase = t * KT + sub * 32;
    const int tid = threadIdx.x;

    int gtid = blockIdx.x * 256 + tid;
    if (gtid < NS * NSLOT)
        g_top2[gtid] = make_float4(-3.4e38f, -3.4e38f, 0.f, 0.f);
    if (gtid == 0) { g_fcount = 0; g_done = 0; }

    if (kbase + 32 <= KK) {
#pragma unroll
        for (int i = 0; i < 4; i++) {
            int it = tid + i * 256;
            int d = it >> 3;
            int k4 = (it & 7) * 4;
            float4 v = *reinterpret_cast<const float4*>(cm + (size_t)d * KK + kbase + k4);
            st[k4 + 0][d] = v.x;
            st[k4 + 1][d] = v.y;
            st[k4 + 2][d] = v.z;
            st[k4 + 3][d] = v.w;
        }
    } else {
#pragma unroll
        for (int i = 0; i < 16; i++) {
            int it = tid + i * 256;
            int d = it >> 5;
            int k = it & 31;
            st[k][d] = (kbase + k < KK) ? cm[(size_t)d * KK + kbase + k] : 0.f;
        }
    }
    __syncthreads();

    // per-k: h_k, ||h_b||, ||r_b||
    {
        int n = tid >> 3, part = tid & 7;
        float sm = 0.f, sh2 = 0.f, sr2 = 0.f;
#pragma unroll
        for (int j = 0; j < 16; j++) {
            float v = st[n][part * 16 + j];
            float h = __half2float(__float2half_rn(v));
            float r = v - h;
            sm = fmaf(v, v, sm);
            sh2 = fmaf(h, h, sh2);
            sr2 = fmaf(r, r, sr2);
        }
#pragma unroll
        for (int off = 4; off; off >>= 1) {
            sm += __shfl_down_sync(0xffffffffu, sm, off);
            sh2 += __shfl_down_sync(0xffffffffu, sh2, off);
            sr2 += __shfl_down_sync(0xffffffffu, sr2, off);
        }
        if (part == 0) {
            if (kbase + n < KK) {
                g_h[kbase + n] = 0.5f * sm;
                atomicMax(&g_maxHb, __float_as_uint(sqrtf(sh2)));
                atomicMax(&g_maxRb, __float_as_uint(sqrtf(sr2)));
            } else {
                g_h[kbase + n] = -3.0e38f;
            }
        }
    }

    // (hi, mid) fp16 split, swizzled image
#pragma unroll
    for (int i = 0; i < 2; i++) {
        int it = tid + i * 256;
        int n = it >> 4;
        int c = it & 15;
        uint4 H, M;
        uint32_t* hp = &H.x; uint32_t* mp = &M.x;
#pragma unroll
        for (int j = 0; j < 4; j++) {
            float v0 = st[n][c * 8 + 2 * j];
            float v1 = st[n][c * 8 + 2 * j + 1];
            __half h0 = __float2half_rn(v0);
            __half h1 = __float2half_rn(v1);
            float r0 = v0 - __half2float(h0);
            float r1 = v1 - __half2float(h1);
            hp[j] = pk2h(v0, v1);
            mp[j] = pk2h(r0, r1);
        }
        int r = sub * 32 + n;
        int ci = r * 16 + (c ^ (r & 7));
        size_t base = (size_t)t * 4096 + ci;
        g_B4[base]        = H;
        g_B4[base + 2048] = M;
    }

    // transposed fp32 copy
#pragma unroll
    for (int i = 0; i < 4; i++) {
        int it = tid + i * 256;
        int n = it >> 5;
        int d4 = (it & 31) * 4;
        float4 w = make_float4(st[n][d4], st[n][d4 + 1], st[n][d4 + 2], st[n][d4 + 3]);
        *reinterpret_cast<float4*>(g_cmT + (size_t)(kbase + n) * DD + d4) = w;
    }
}

// ---------------------------------------------------------------------------
__device__ __forceinline__ void stageB_hi(uint32_t sb, int tid, int kc, int buf) {
    const uint4* src = g_B4 + (size_t)kc * 4096;   // hi split = first 2048 uint4
    uint32_t dst = sb + OFF_B + (uint32_t)buf * BUFB;
#pragma unroll
    for (int i = 0; i < 8; i++)
        cp16(dst + (uint32_t)(tid + i * 256) * 16, src + tid + i * 256);
    if (tid < 32)
        cp16(sb + OFF_H + (uint32_t)buf * 512 + (uint32_t)tid * 16,
             (const char*)g_h + (size_t)kc * 512 + (size_t)tid * 16);
    CP_COMMIT();
}

__device__ __forceinline__ void buildA_hi(char* smem, const float* __restrict__ x,
                                          int n0, int tid) {
    const int row = tid >> 1;
    const int c0 = (tid & 1) * 8;
    const float4* xr = reinterpret_cast<const float4*>(x + (size_t)(n0 + row) * DD);
    uint4* As = reinterpret_cast<uint4*>(smem + OFF_A);
#pragma unroll
    for (int c = 0; c < 8; c++) {
        float4 p = xr[(c0 + c) * 2];
        float4 q = xr[(c0 + c) * 2 + 1];
        uint4 H;
        H.x = pk2h(p.x, p.y);
        H.y = pk2h(p.z, p.w);
        H.z = pk2h(q.x, q.y);
        H.w = pk2h(q.z, q.w);
        As[row * 16 + ((c0 + c) ^ (row & 7))] = H;
    }
}

// top-2 merge
#define T2_MERGE(B1, I1, B2, c1, j1, c2)                          \
    do {                                                          \
        float _nb2 = fmaxf(fminf(B1, c1), fmaxf(B2, c2));         \
        bool _win = (c1 > B1) || (c1 == B1 && (j1) < (I1));       \
        if (_win) { B1 = c1; I1 = j1; }                           \
        B2 = _nb2;                                                \
    } while (0)

__device__ void flush_fn(char* smem, int st_, int bid, const float* b1v,
                         const int* i1v, const float* b2v, int tid, int lane,
                         int mwarp, int nwarp) {
    float* sb1 = reinterpret_cast<float*>(smem + OFF_B);   // B buffers are idle
    int*   si1 = reinterpret_cast<int*>(smem + OFF_B + 2048);
    float* sb2 = reinterpret_cast<float*>(smem + OFF_B + 4096);
    __syncthreads();
#pragma unroll
    for (int s = 0; s < 8; s++) {
        float B1 = b1v[s]; int I1 = i1v[s]; float B2 = b2v[s];
#pragma unroll
        for (int off = 1; off < 4; off <<= 1) {
            float o1 = __shfl_xor_sync(0xffffffffu, B1, off);
            int   oi = __shfl_xor_sync(0xffffffffu, I1, off);
            float o2 = __shfl_xor_sync(0xffffffffu, B2, off);
            T2_MERGE(B1, I1, B2, o1, oi, o2);
        }
        if ((lane & 3) == 0) {
            int row = mwarp * 64 + (s >> 1) * 16 + (s & 1) * 8 + (lane >> 2);
            sb1[row * 4 + nwarp] = B1;
            si1[row * 4 + nwarp] = I1;
            sb2[row * 4 + nwarp] = B2;
        }
    }
    __syncthreads();
    if (tid < 128) {
        float B1 = sb1[tid * 4]; int I1 = si1[tid * 4]; float B2 = sb2[tid * 4];
#pragma unroll
        for (int w = 1; w < 4; w++) {
            float c1 = sb1[tid * 4 + w];
            int   j1 = si1[tid * 4 + w];
            float c2 = sb2[tid * 4 + w];
            T2_MERGE(B1, I1, B2, c1, j1, c2);
        }
        int slot = bid - cta_of(st_ * NT2);
        g_top2[(st_ * TM + tid) * NSLOT + slot] =
            make_float4(B1, B2, __int_as_float(I1), 0.f);
    }
    __syncthreads();
}

// ---------------------------------------------------------------------------
// phase 1: persistent 148 CTAs (occ 1); A fragments REGISTER-RESIDENT across
// the whole sample tile -> inner loop is 2 LDSM + 16 MMA per k-step (dense,
// fallback2-style). 1-product hh GEMM + running top-2.
// NOTE: flush_fn scratch uses the B-buffer region; it runs only when all
// staged B data for the old tile has been consumed (tile boundary), and the
// next tile's first B stage is issued AFTER the flush completes.
// ---------------------------------------------------------------------------
__global__ void __launch_bounds__(256, 1)
vq_main(const float* __restrict__ x) {
    extern __shared__ __align__(1024) char smem[];
    const uint32_t sb = smem_u32(smem);
    const int tid = threadIdx.x;
    const int wid = tid >> 5;
    const int lane = tid & 31;
    const int l8 = lane & 7;
    const int g = lane >> 3;
    const int mwarp = wid >> 2;
    const int nwarp = wid & 3;
    const int bid = blockIdx.x;

    const int start = bid * 68 + min(bid, 48);
    const int count = 68 + (bid < 48 ? 1 : 0);

    const uint32_t AQ  = sb + OFF_A + (uint32_t)mwarp * 16384u
                       + (uint32_t)l8 * 272 + ((uint32_t)(g & 1) << 11);
    const uint32_t gxa = (uint32_t)(g >> 1) << 4;
    const uint32_t gxb = (uint32_t)(g & 1) << 4;
    const uint32_t BQg = (uint32_t)nwarp * 8192u
                       + ((uint32_t)(g >> 1) << 11) + (uint32_t)l8 * 272;

    uint32_t Ar[8][4][4];          // register-resident A fragments (128 regs)

    int cur_st = start / NT2;
    // build A image, then hoist fragments to registers
    buildA_hi(smem, x, cur_st * TM, tid);
    __syncthreads();
#pragma unroll
    for (int ks = 0; ks < 8; ks++) {
        const uint32_t kxa = ((uint32_t)ks << 5) | gxa;
#pragma unroll
        for (int ma = 0; ma < 4; ma++)
            LDSM4(Ar[ks][ma], (AQ + (uint32_t)ma * 4096) ^ kxa);
    }
    stageB_hi(sb, tid, start - cur_st * NT2, 0);

    float b1v[8], b2v[8];
    int   i1v[8];
#pragma unroll
    for (int i = 0; i < 8; i++) { b1v[i] = -3.4e38f; b2v[i] = -3.4e38f; i1v[i] = 0; }

    for (int i = 0; i < count; i++) {
        const int u = start + i;
        const int stt = u / NT2;
        const int kc = u - stt * NT2;
        const int b = i & 1;

        if (stt != cur_st) {
            // drain any in-flight B stage into the buffer we are about to reuse
            asm volatile("cp.async.wait_group 0;" ::: "memory");
            flush_fn(smem, cur_st, bid, b1v, i1v, b2v, tid, lane, mwarp, nwarp);
            buildA_hi(smem, x, stt * TM, tid);
            __syncthreads();
#pragma unroll
            for (int ks = 0; ks < 8; ks++) {
                const uint32_t kxa = ((uint32_t)ks << 5) | gxa;
#pragma unroll
                for (int ma = 0; ma < 4; ma++)
                    LDSM4(Ar[ks][ma], (AQ + (uint32_t)ma * 4096) ^ kxa);
            }
            stageB_hi(sb, tid, kc, b);     // restage current unit (flush used B region)
            cur_st = stt;
#pragma unroll
            for (int s = 0; s < 8; s++) { b1v[s] = -3.4e38f; b2v[s] = -3.4e38f; i1v[s] = 0; }
        }

        // prefetch next unit's B unless it belongs to a new tile (flush path restages)
        const bool next_same_tile = (i + 1 < count) && ((u + 1) / NT2 == stt);
        if (next_same_tile) {
            stageB_hi(sb, tid, (u + 1) - stt * NT2, (i + 1) & 1);
            asm volatile("cp.async.wait_group 1;" ::: "memory");
        } else {
            asm volatile("cp.async.wait_group 0;" ::: "memory");
        }
        __syncthreads();

        const uint32_t Bt = sb + OFF_B + (uint32_t)b * BUFB + BQg;
        float acc[4][4][4];
#pragma unroll
        for (int ma = 0; ma < 4; ma++)
#pragma unroll
            for (int nn = 0; nn < 4; nn++)
#pragma unroll
                for (int r = 0; r < 4; r++) acc[ma][nn][r] = 0.f;

#pragma unroll
        for (int ks = 0; ks < 8; ks++) {
            const uint32_t kxb = ((uint32_t)ks << 5) | gxb;
            uint32_t bf[2][4];
#pragma unroll
            for (int nb = 0; nb < 2; nb++)
                LDSM4(bf[nb], (Bt + (uint32_t)nb * 4096) ^ kxb);
#pragma unroll
            for (int ma = 0; ma < 4; ma++)
#pragma unroll
                for (int nn = 0; nn < 4; nn++)
                    MMA(acc[ma][nn], Ar[ks][ma],
                        bf[nn >> 1][2 * (nn & 1)], bf[nn >> 1][2 * (nn & 1) + 1]);
        }

        const float* hb = reinterpret_cast<const float*>(smem + OFF_H + b * 512);
        const int kbase = kc * KT + nwarp * 32 + (lane & 3) * 2;
#pragma unroll
        for (int ma = 0; ma < 4; ma++) {
            float c0[8], c1[8];
#pragma unroll
            for (int nn = 0; nn < 4; nn++) {
                int hi0 = nwarp * 32 + nn * 8 + (lane & 3) * 2;
                float h0 = hb[hi0], h1 = hb[hi0 + 1];
                c0[2 * nn]     = h0 - acc[ma][nn][0];
                c0[2 * nn + 1] = h1 - acc[ma][nn][1];
                c1[2 * nn]     = h0 - acc[ma][nn][2];
                c1[2 * nn + 1] = h1 - acc[ma][nn][3];
            }
#pragma unroll
            for (int rh = 0; rh < 2; rh++) {
                const float* cc = rh ? c1 : c0;
                const int s = 2 * ma + rh;
                float gm = cc[0];
#pragma unroll
                for (int q = 1; q < 8; q++) gm = fmaxf(gm, cc[q]);
                if (gm > b2v[s]) {
#pragma unroll
                    for (int q = 0; q < 8; q++) {
                        float d = cc[q];
                        int k = kbase + (q >> 1) * 8 + (q & 1);
                        if (d > b1v[s]) { b2v[s] = b1v[s]; b1v[s] = d; i1v[s] = k; }
                        else b2v[s] = fmaxf(b2v[s], d);
                    }
                }
            }
        }
        __syncthreads();
    }

    flush_fn(smem, cur_st, bid, b1v, i1v, b2v, tid, lane, mwarp, nwarp);
}

// ---------------------------------------------------------------------------
// decision: certified gap -> index; else flag for fallback. grid = 2048 x 256.
// ---------------------------------------------------------------------------
__global__ void decision_kernel(const float* __restrict__ x) {
    const int lane = threadIdx.x & 31;
    const int n = blockIdx.x * 8 + (threadIdx.x >> 5);
    float4 xv = reinterpret_cast<const float4*>(x)[n * 32 + lane];
    float sh2 = 0.f, sr2 = 0.f;
    float vv[4] = {xv.x, xv.y, xv.z, xv.w};
#pragma unroll
    for (int j = 0; j < 4; j++) {
        float h = __half2float(__float2half_rn(vv[j]));
        float r = vv[j] - h;
        sh2 = fmaf(h, h, sh2);
        sr2 = fmaf(r, r, sr2);
    }
#pragma unroll
    for (int off = 16; off; off >>= 1) {
        sh2 += __shfl_xor_sync(0xffffffffu, sh2, off);
        sr2 += __shfl_xor_sync(0xffffffffu, sr2, off);
    }
    if (lane == 0) {
        float Hbm = __uint_as_float(g_maxHb);
        float Rbm = __uint_as_float(g_maxRb);
        float nh = sqrtf(sh2), nr = sqrtf(sr2);
        float E = (nh * Rbm + nr * Hbm + nr * Rbm) * 1.001f + 4e-3f;

        float4 t0 = g_top2[n * NSLOT + 0];
        float B1 = t0.x, B2 = t0.y;
        int I1 = __float_as_int(t0.z);
#pragma unroll
        for (int sl = 1; sl < NSLOT; sl++) {
            float4 tv = g_top2[n * NSLOT + sl];
            float c1 = tv.x, c2 = tv.y;
            int j1 = __float_as_int(tv.z);
            T2_MERGE(B1, I1, B2, c1, j1, c2);
        }
        if (B1 - B2 > 2.f * E) {
            g_idx[n] = I1;
        } else {
            g_idx[n] = -1;
            g_bestu64[n] = 0ull;
            int p = atomicAdd(&g_fcount, 1);
            g_flist[p] = n;
        }
    }
}

// ---------------------------------------------------------------------------
// fallback2: 3-product MMA rescan of flagged samples. Contiguous unit ranges,
// double-buffered B, atomicMax publish (commutative, deterministic).
// ---------------------------------------------------------------------------
__global__ void __launch_bounds__(256, 1)
fallback2_kernel(const float* __restrict__ x) {
    extern __shared__ __align__(1024) char smem[];
    const uint32_t sb = smem_u32(smem);
    const int tid = threadIdx.x;
    const int wid = tid >> 5;
    const int lane = tid & 31;
    const int l8 = lane & 7;
    const int gg = lane >> 3;
    const int mwarp = wid >> 2;
    const int nwarp = wid & 3;

    const int fcount = g_fcount;
    if (fcount == 0) return;
    const int nG = (fcount + 127) >> 7;
    const int total = nG * NT2;
    const int base = total / GRID;
    const int rem = total - base * GRID;
    const int start = blockIdx.x * base + min((int)blockIdx.x, rem);
    const int count = base + (blockIdx.x < rem ? 1 : 0);
    if (count == 0) return;

    int* sids = reinterpret_cast<int*>(smem + F2_OFF_S);

    const uint32_t AQ  = sb + F2_OFF_A + (uint32_t)mwarp * 16384u
                       + (uint32_t)l8 * 272 + ((uint32_t)(gg & 1) << 11);
    const uint32_t gxa = (uint32_t)(gg >> 1) << 4;
    const uint32_t gxb = (uint32_t)(gg & 1) << 4;
    const uint32_t BQ0 = sb + F2_OFF_B + (uint32_t)nwarp * 8192u
                       + ((uint32_t)(gg >> 1) << 11) + (uint32_t)l8 * 272;

    int cur_gi = start / NT2;
    {
        const int kt0 = start - cur_gi * NT2;
        const uint4* src = g_B4 + (size_t)kt0 * 4096;
#pragma unroll
        for (int i = 0; i < 16; i++)
            cp16(sb + F2_OFF_B + (uint32_t)(tid + i * 256) * 16, src + tid + i * 256);
        if (tid < 32)
            cp16(sb + F2_OFF_H + (uint32_t)tid * 16,
                 (const char*)g_h + (size_t)kt0 * 512 + (size_t)tid * 16);
        CP_COMMIT();
    }
    if (tid < 128) {
        int fi = cur_gi * 128 + tid;
        sids[tid] = (fi < fcount) ? g_flist[fi] : -1;
    }
    __syncthreads();

    auto buildA = [&](void) {
        const int row = tid >> 1;
        const int c0 = (tid & 1) * 8;
        const int n = sids[row];
        uint4* As = reinterpret_cast<uint4*>(smem + F2_OFF_A);
        if (n >= 0) {
            const float4* xr = reinterpret_cast<const float4*>(x + (size_t)n * DD);
#pragma unroll
            for (int c = 0; c < 8; c++) {
                float4 p = xr[(c0 + c) * 2];
                float4 q = xr[(c0 + c) * 2 + 1];
                float v[8] = {p.x, p.y, p.z, p.w, q.x, q.y, q.z, q.w};
                uint4 H, M;
                uint32_t* hp = &H.x; uint32_t* mp = &M.x;
#pragma unroll
                for (int j = 0; j < 4; j++) {
                    float v0 = v[2 * j], v1 = v[2 * j + 1];
                    __half h0 = __float2half_rn(v0);
                    __half h1 = __float2half_rn(v1);
                    float r0 = v0 - __half2float(h0);
                    float r1 = v1 - __half2float(h1);
                    hp[j] = pk2h(v0, v1);
                    mp[j] = pk2h(r0, r1);
                }
                int ci = row * 16 + ((c0 + c) ^ (row & 7));
                As[ci] = H;
                As[ci + 2048] = M;
            }
        } else {
            uint4 Z = make_uint4(0, 0, 0, 0);
#pragma unroll
            for (int c = 0; c < 8; c++) {
                int ci = row * 16 + ((c0 + c) ^ (row & 7));
                As[ci] = Z;
                As[ci + 2048] = Z;
            }
        }
    };
    buildA();

    for (int i = 0; i < count; i++) {
        const int u = start + i;
        const int gi = u / NT2;
        const int kt = u - gi * NT2;
        const int b = i & 1;

        if (gi != cur_gi) {
            __syncthreads();
            if (tid < 128) {
                int fi = gi * 128 + tid;
                sids[tid] = (fi < fcount) ? g_flist[fi] : -1;
            }
            __syncthreads();
            buildA();
            cur_gi = gi;
        }

        if (i + 1 < count) {
            const int u2 = start + i + 1;
            const int kt2 = u2 - (u2 / NT2) * NT2;
            const uint4* src = g_B4 + (size_t)kt2 * 4096;
            uint32_t dst = sb + F2_OFF_B + (uint32_t)((i + 1) & 1) * F2_BUFB;
#pragma unroll
            for (int j = 0; j < 16; j++)
                cp16(dst + (uint32_t)(tid + j * 256) * 16, src + tid + j * 256);
            if (tid < 32)
                cp16(sb + F2_OFF_H + (uint32_t)((i + 1) & 1) * 512 + (uint32_t)tid * 16,
                     (const char*)g_h + (size_t)kt2 * 512 + (size_t)tid * 16);
            CP_COMMIT();
            asm volatile("cp.async.wait_group 1;" ::: "memory");
        } else {
            asm volatile("cp.async.wait_group 0;" ::: "memory");
        }
        __syncthreads();

        const uint32_t Bt = BQ0 + (uint32_t)b * F2_BUFB;
        float acc[4][4][4];
#pragma unroll
        for (int ma = 0; ma < 4; ma++)
#pragma unroll
            for (int nn = 0; nn < 4; nn++)
#pragma unroll
                for (int r = 0; r < 4; r++) acc[ma][nn][r] = 0.f;

#pragma unroll
        for (int ks = 0; ks < 8; ks++) {
            const uint32_t kxa = ((uint32_t)ks << 5) | gxa;
            const uint32_t kxb = ((uint32_t)ks << 5) | gxb;
            uint32_t a[2][4][4];
            uint32_t bf[2][2][4];
#pragma unroll
            for (int s = 0; s < 2; s++)
#pragma unroll
                for (int ma = 0; ma < 4; ma++)
                    LDSM4(a[s][ma],
                          (AQ + (uint32_t)s * 32768 + (uint32_t)ma * 4096) ^ kxa);
#pragma unroll
            for (int s = 0; s < 2; s++)
#pragma unroll
                for (int nb = 0; nb < 2; nb++)
                    LDSM4(bf[s][nb],
                          (Bt + (uint32_t)s * 32768 + (uint32_t)nb * 4096) ^ kxb);

            const int PA[3] = {0, 0, 1};
            const int PB[3] = {0, 1, 0};
#pragma unroll
            for (int p = 0; p < 3; p++)
#pragma unroll
                for (int ma = 0; ma < 4; ma++)
#pragma unroll
                    for (int nn = 0; nn < 4; nn++)
                        MMA(acc[ma][nn], a[PA[p]][ma],
                            bf[PB[p]][nn >> 1][2 * (nn & 1)],
                            bf[PB[p]][nn >> 1][2 * (nn & 1) + 1]);
        }

        const float* hb = reinterpret_cast<const float*>(smem + F2_OFF_H + b * 512);
        float* sbv = reinterpret_cast<float*>(smem + F2_OFF_R);
        int*   siv = reinterpret_cast<int*>(smem + F2_OFF_R + 2048);
#pragma unroll
        for (int ma = 0; ma < 4; ma++)
#pragma unroll
            for (int rh = 0; rh < 2; rh++) {
                float bv = -3.4e38f;
                int bix = 0;
#pragma unroll
                for (int nn = 0; nn < 4; nn++) {
                    int hi0 = nwarp * 32 + nn * 8 + (lane & 3) * 2;
                    float d0 = hb[hi0] - acc[ma][nn][2 * rh];
                    float d1 = hb[hi0 + 1] - acc[ma][nn][2 * rh + 1];
                    int k0 = kt * KT + hi0;
                    if (d0 > bv) { bv = d0; bix = k0; }
                    if (d1 > bv) { bv = d1; bix = k0 + 1; }
                }
#pragma unroll
                for (int off = 1; off < 4; off <<= 1) {
                    float ov = __shfl_xor_sync(0xffffffffu, bv, off);
                    int   oi = __shfl_xor_sync(0xffffffffu, bix, off);
                    if (ov > bv || (ov == bv && oi < bix)) { bv = ov; bix = oi; }
                }
                if ((lane & 3) == 0) {
                    int row = mwarp * 64 + ma * 16 + rh * 8 + (lane >> 2);
                    sbv[row * 4 + nwarp] = bv;
                    siv[row * 4 + nwarp] = bix;
                }
            }
        __syncthreads();
        if (tid < 128) {
            float bv = sbv[tid * 4];
            int bix = siv[tid * 4];
#pragma unroll
            for (int w = 1; w < 4; w++) {
                float v = sbv[tid * 4 + w];
                int ix = siv[tid * 4 + w];
                if (v > bv || (v == bv && ix < bix)) { bv = v; bix = ix; }
            }
            int sid = sids[tid];
            if (sid >= 0) {
                unsigned long long key =
                    ((unsigned long long)enc_f(bv) << 32)
                    | (unsigned long long)(0xFFFFFFFFu - (unsigned)bix);
                atomicMax(&g_bestu64[sid], key);
            }
        }
        __syncthreads();
    }
}

// ---------------------------------------------------------------------------
// gather quantize + index output + MSE (last block folds final reduction)
// ---------------------------------------------------------------------------
__global__ void gather_kernel(const float* __restrict__ x,
                              float* __restrict__ out) {
    __shared__ float red[256];
    __shared__ bool last;
    const int tid = threadIdx.x;
    float* out_q = out;
    float* out_idx_f = out + (size_t)NS * DD;

    int gt = blockIdx.x * 256 + tid;
    if (gt < NS) {
        int ix = g_idx[gt];
        if (ix < 0)
            ix = (int)(0xFFFFFFFFu - (unsigned)(g_bestu64[gt] & 0xFFFFFFFFull));
        out_idx_f[gt] = (float)ix;
    }

    float local = 0.f;
    for (int e4 = blockIdx.x * 256 + tid; e4 < NS * DD / 4;
         e4 += gridDim.x * 256) {
        int n = e4 >> 5;
        int d4 = (e4 & 31) * 4;
        int ix = g_idx[n];
        if (ix < 0)
            ix = (int)(0xFFFFFFFFu - (unsigned)(g_bestu64[n] & 0xFFFFFFFFull));
        float4 q = *reinterpret_cast<const float4*>(g_cmT + (size_t)ix * DD + d4);
        float4 xv = reinterpret_cast<const float4*>(x)[e4];
        reinterpret_cast<float4*>(out_q)[e4] = q;
        float a = xv.x - q.x, b = xv.y - q.y, c = xv.z - q.z, d = xv.w - q.w;
        local = fmaf(a, a, local);
        local = fmaf(b, b, local);
        local = fmaf(c, c, local);
        local = fmaf(d, d, local);
    }
    red[tid] = local;
    __syncthreads();
    for (int s = 128; s; s >>= 1) {
        if (tid < s) red[tid] += red[tid + s];
        __syncthreads();
    }
    if (tid == 0) {
        g_partial[blockIdx.x] = red[0];
        __threadfence();
        unsigned t = atomicAdd(&g_done, 1u);
        last = (t == gridDim.x - 1);
    }
    __syncthreads();
    if (last) {
        __threadfence();
        volatile float* gp = g_partial;
        __shared__ double dred[256];
        double acc = 0.0;
        for (int i = tid; i < 1024; i += 256) acc += (double)gp[i];
        dred[tid] = acc;
        __syncthreads();
        for (int st = 128; st; st >>= 1) {
            if (tid < st) dred[tid] += dred[tid + st];
            __syncthreads();
        }
        if (tid == 0)
            out[(size_t)NS * DD + NS] =
                (float)(dred[0] / (double)((size_t)NS * DD));
    }
}

// ---------------------------------------------------------------------------
extern "C" void kernel_launch(void* const* d_in, const int* in_sizes, int n_in,
                              void* d_out, int out_size) {
    const float* x  = (const float*)d_in[0];   // [16384, 128]
    const float* cm = (const float*)d_in[1];   // [128, 10000]
    float* out = (float*)d_out;                // [quantize | index | diff]

    cudaFuncSetAttribute(vq_main,
                         cudaFuncAttributeMaxDynamicSharedMemorySize, SMEM_TOTAL);
    cudaFuncSetAttribute(fallback2_kernel,
                         cudaFuncAttributeMaxDynamicSharedMemorySize, F2_SMEM);

    prepB_kernel<<<NT2 * 4, 256>>>(cm);
    vq_main<<<GRID, 256, SMEM_TOTAL>>>(x);
    decision_kernel<<<NS / 8, 256>>>(x);
    fallback2_kernel<<<GRID, 256, F2_SMEM>>>(x);
    gather_kernel<<<1024, 256>>>(x, out);
}

// round 15
// speedup vs baseline: 1.1584x; 1.1584x over previous
#include <cuda_runtime.h>
#include <cuda_fp16.h>
#include <cstdint>

#define NS   16384
#define DD   128
#define KK   10000
#define KT   128
#define NT2  79             // k-tiles; 79*128 = 10112
#define KPAD (NT2 * KT)
#define TM   128
#define GRID 148
#define GRID2 296           // vq_main: 2 CTAs/SM
#define NSLOT 4             // max CTAs covering one sample tile

// ---- vq_main smem layout (hi split only) ----
#define OFF_A  0            // 32768: x-tile hi split, swizzled fp16
#define OFF_B  32768        // 2 x 32768 buffers
#define BUFB   32768
#define OFF_H  98304        // 2 x 512
#define SMEM_TOTAL (OFF_H + 1024)

// ---- fallback2 smem layout (hi+mid splits) ----
#define F2_OFF_A 0          // 2 x 32768 (hi, mid)
#define F2_OFF_B 65536      // 65536 (hi|mid), single buffer
#define F2_OFF_H 131072     // 512
#define F2_OFF_S 131584     // 128 ints (sample ids)
#define F2_SMEM  (F2_OFF_S + 512)

__device__ uint4 g_B4[(size_t)NT2 * 4096];               // hi+mid swizzled B tiles
__device__ __align__(16) float g_cmT[(size_t)KPAD * DD]; // transposed means [k][d]
__device__ __align__(16) float g_h[KPAD];                // 0.5*||m||^2 (pad -> -3e38)
__device__ __align__(16) float4 g_top2[NS * NSLOT];      // per (sample, slot): b1,b2,i1
__device__ unsigned g_maxHb = 0;                         // max_k ||h_b|| (float bits)
__device__ unsigned g_maxRb = 0;                         // max_k ||r_b||
__device__ int g_fcount;
__device__ int g_flist[NS];
__device__ unsigned long long g_bestu64[NS];
__device__ int   g_idx[NS];
__device__ float g_partial[1024];
__device__ unsigned g_done;

// ---------------------------------------------------------------------------
__device__ __forceinline__ uint32_t smem_u32(const void* p) {
    uint32_t a;
    asm("{ .reg .u64 t; cvta.to.shared.u64 t, %1; cvt.u32.u64 %0, t; }"
        : "=r"(a) : "l"(p));
    return a;
}
__device__ __forceinline__ void cp16(uint32_t daddr, const void* src) {
    asm volatile("cp.async.cg.shared.global [%0], [%1], 16;"
                 :: "r"(daddr), "l"(src) : "memory");
}
#define CP_COMMIT() asm volatile("cp.async.commit_group;" ::: "memory")

#define LDSM4(R, addr)                                                        \
    asm volatile("ldmatrix.sync.aligned.m8n8.x4.shared.b16 {%0,%1,%2,%3}, [%4];" \
                 : "=r"((R)[0]), "=r"((R)[1]), "=r"((R)[2]), "=r"((R)[3])     \
                 : "r"(addr))

#define MMA(D, A, B0, B1)                                                     \
    asm volatile("mma.sync.aligned.m16n8k16.row.col.f32.f16.f16.f32 "         \
                 "{%0,%1,%2,%3}, {%4,%5,%6,%7}, {%8,%9}, {%0,%1,%2,%3};"      \
                 : "+f"((D)[0]), "+f"((D)[1]), "+f"((D)[2]), "+f"((D)[3])     \
                 : "r"((A)[0]), "r"((A)[1]), "r"((A)[2]), "r"((A)[3]),        \
                   "r"(B0), "r"(B1))

__device__ __forceinline__ unsigned pk2h(float a, float b) {
    __half2 t = __floats2half2_rn(a, b);
    return *reinterpret_cast<unsigned*>(&t);
}
__device__ __forceinline__ unsigned enc_f(float f) {
    unsigned s = __float_as_uint(f);
    return (s & 0x80000000u) ? ~s : (s | 0x80000000u);
}
// partition for GRID2=296: 48 CTAs of 35 units, 248 of 34
__device__ __forceinline__ int cta_of(int u) {
    return (u < 48 * 35) ? (u / 35) : (48 + (u - 48 * 35) / 34);
}

// ---------------------------------------------------------------------------
// prep: transpose cm per 32-cluster sub-tile; (hi, mid) fp16 B image; cmT;
// h_k; per-k norm maxes; zero g_top2 / g_fcount / g_done. grid = 316 x 256.
// ---------------------------------------------------------------------------
__global__ void prepB_kernel(const float* __restrict__ cm) {
    __shared__ float st[32][132];
    const int t = blockIdx.x >> 2;
    const int sub = blockIdx.x & 3;
    const int kbase = t * KT + sub * 32;
    const int tid = threadIdx.x;

    int gtid = blockIdx.x * 256 + tid;
    if (gtid < NS * NSLOT)
        g_top2[gtid] = make_float4(-3.4e38f, -3.4e38f, 0.f, 0.f);
    if (gtid == 0) { g_fcount = 0; g_done = 0; }

    if (kbase + 32 <= KK) {
#pragma unroll
        for (int i = 0; i < 4; i++) {
            int it = tid + i * 256;
            int d = it >> 3;
            int k4 = (it & 7) * 4;
            float4 v = *reinterpret_cast<const float4*>(cm + (size_t)d * KK + kbase + k4);
            st[k4 + 0][d] = v.x;
            st[k4 + 1][d] = v.y;
            st[k4 + 2][d] = v.z;
            st[k4 + 3][d] = v.w;
        }
    } else {
#pragma unroll
        for (int i = 0; i < 16; i++) {
            int it = tid + i * 256;
            int d = it >> 5;
            int k = it & 31;
            st[k][d] = (kbase + k < KK) ? cm[(size_t)d * KK + kbase + k] : 0.f;
        }
    }
    __syncthreads();

    // per-k: h_k, ||h_b||, ||r_b||
    {
        int n = tid >> 3, part = tid & 7;
        float sm = 0.f, sh2 = 0.f, sr2 = 0.f;
#pragma unroll
        for (int j = 0; j < 16; j++) {
            float v = st[n][part * 16 + j];
            float h = __half2float(__float2half_rn(v));
            float r = v - h;
            sm = fmaf(v, v, sm);
            sh2 = fmaf(h, h, sh2);
            sr2 = fmaf(r, r, sr2);
        }
#pragma unroll
        for (int off = 4; off; off >>= 1) {
            sm += __shfl_down_sync(0xffffffffu, sm, off);
            sh2 += __shfl_down_sync(0xffffffffu, sh2, off);
            sr2 += __shfl_down_sync(0xffffffffu, sr2, off);
        }
        if (part == 0) {
            if (kbase + n < KK) {
                g_h[kbase + n] = 0.5f * sm;
                atomicMax(&g_maxHb, __float_as_uint(sqrtf(sh2)));
                atomicMax(&g_maxRb, __float_as_uint(sqrtf(sr2)));
            } else {
                g_h[kbase + n] = -3.0e38f;
            }
        }
    }

    // (hi, mid) fp16 split, swizzled image
#pragma unroll
    for (int i = 0; i < 2; i++) {
        int it = tid + i * 256;
        int n = it >> 4;
        int c = it & 15;
        uint4 H, M;
        uint32_t* hp = &H.x; uint32_t* mp = &M.x;
#pragma unroll
        for (int j = 0; j < 4; j++) {
            float v0 = st[n][c * 8 + 2 * j];
            float v1 = st[n][c * 8 + 2 * j + 1];
            __half h0 = __float2half_rn(v0);
            __half h1 = __float2half_rn(v1);
            float r0 = v0 - __half2float(h0);
            float r1 = v1 - __half2float(h1);
            hp[j] = pk2h(v0, v1);
            mp[j] = pk2h(r0, r1);
        }
        int r = sub * 32 + n;
        int ci = r * 16 + (c ^ (r & 7));
        size_t base = (size_t)t * 4096 + ci;
        g_B4[base]        = H;
        g_B4[base + 2048] = M;
    }

    // transposed fp32 copy
#pragma unroll
    for (int i = 0; i < 4; i++) {
        int it = tid + i * 256;
        int n = it >> 5;
        int d4 = (it & 31) * 4;
        float4 w = make_float4(st[n][d4], st[n][d4 + 1], st[n][d4 + 2], st[n][d4 + 3]);
        *reinterpret_cast<float4*>(g_cmT + (size_t)(kbase + n) * DD + d4) = w;
    }
}

// ---------------------------------------------------------------------------
__device__ __forceinline__ void stageB_hi(uint32_t sb, int tid, int kc, int buf) {
    const uint4* src = g_B4 + (size_t)kc * 4096;   // hi split = first 2048 uint4
    uint32_t dst = sb + OFF_B + (uint32_t)buf * BUFB;
#pragma unroll
    for (int i = 0; i < 8; i++)
        cp16(dst + (uint32_t)(tid + i * 256) * 16, src + tid + i * 256);
    if (tid < 32)
        cp16(sb + OFF_H + (uint32_t)buf * 512 + (uint32_t)tid * 16,
             (const char*)g_h + (size_t)kc * 512 + (size_t)tid * 16);
    CP_COMMIT();
}

__device__ __forceinline__ void buildA_hi(char* smem, const float* __restrict__ x,
                                          int n0, int tid) {
    const int row = tid >> 1;
    const int c0 = (tid & 1) * 8;
    const float4* xr = reinterpret_cast<const float4*>(x + (size_t)(n0 + row) * DD);
    uint4* As = reinterpret_cast<uint4*>(smem + OFF_A);
#pragma unroll
    for (int c = 0; c < 8; c++) {
        float4 p = xr[(c0 + c) * 2];
        float4 q = xr[(c0 + c) * 2 + 1];
        uint4 H;
        H.x = pk2h(p.x, p.y);
        H.y = pk2h(p.z, p.w);
        H.z = pk2h(q.x, q.y);
        H.w = pk2h(q.z, q.w);
        As[row * 16 + ((c0 + c) ^ (row & 7))] = H;
    }
}

// top-2 merge
#define T2_MERGE(B1, I1, B2, c1, j1, c2)                          \
    do {                                                          \
        float _nb2 = fmaxf(fminf(B1, c1), fmaxf(B2, c2));         \
        bool _win = (c1 > B1) || (c1 == B1 && (j1) < (I1));       \
        if (_win) { B1 = c1; I1 = j1; }                           \
        B2 = _nb2;                                                \
    } while (0)

__device__ void flush_fn(char* smem, int st_, int bid, const float* b1v,
                         const int* i1v, const float* b2v, int tid, int lane,
                         int mwarp, int nwarp) {
    float* sb1 = reinterpret_cast<float*>(smem);
    int*   si1 = reinterpret_cast<int*>(smem + 2048);
    float* sb2 = reinterpret_cast<float*>(smem + 4096);
    __syncthreads();
#pragma unroll
    for (int s = 0; s < 8; s++) {
        float B1 = b1v[s]; int I1 = i1v[s]; float B2 = b2v[s];
#pragma unroll
        for (int off = 1; off < 4; off <<= 1) {
            float o1 = __shfl_xor_sync(0xffffffffu, B1, off);
            int   oi = __shfl_xor_sync(0xffffffffu, I1, off);
            float o2 = __shfl_xor_sync(0xffffffffu, B2, off);
            T2_MERGE(B1, I1, B2, o1, oi, o2);
        }
        if ((lane & 3) == 0) {
            int row = mwarp * 64 + (s >> 1) * 16 + (s & 1) * 8 + (lane >> 2);
            sb1[row * 4 + nwarp] = B1;
            si1[row * 4 + nwarp] = I1;
            sb2[row * 4 + nwarp] = B2;
        }
    }
    __syncthreads();
    if (tid < 128) {
        float B1 = sb1[tid * 4]; int I1 = si1[tid * 4]; float B2 = sb2[tid * 4];
#pragma unroll
        for (int w = 1; w < 4; w++) {
            float c1 = sb1[tid * 4 + w];
            int   j1 = si1[tid * 4 + w];
            float c2 = sb2[tid * 4 + w];
            T2_MERGE(B1, I1, B2, c1, j1, c2);
        }
        int slot = bid - cta_of(st_ * NT2);
        g_top2[(st_ * TM + tid) * NSLOT + slot] =
            make_float4(B1, B2, __int_as_float(I1), 0.f);
    }
    __syncthreads();
}

// ---------------------------------------------------------------------------
// phase 1: persistent 296 CTAs (2/SM); 1-product hh GEMM + running top-2.
// (byte-identical to the proven round-9 kernel)
// ---------------------------------------------------------------------------
__global__ void __launch_bounds__(256, 2)
vq_main(const float* __restrict__ x) {
    extern __shared__ __align__(1024) char smem[];
    const uint32_t sb = smem_u32(smem);
    const int tid = threadIdx.x;
    const int wid = tid >> 5;
    const int lane = tid & 31;
    const int l8 = lane & 7;
    const int g = lane >> 3;
    const int mwarp = wid >> 2;
    const int nwarp = wid & 3;
    const int bid = blockIdx.x;

    const int start = bid * 34 + min(bid, 48);
    const int count = 34 + (bid < 48 ? 1 : 0);

    int cur_st = start / NT2;
    stageB_hi(sb, tid, start - cur_st * NT2, 0);
    buildA_hi(smem, x, cur_st * TM, tid);

    const uint32_t AQ  = sb + OFF_A + (uint32_t)mwarp * 16384u
                       + (uint32_t)l8 * 272 + ((uint32_t)(g & 1) << 11);
    const uint32_t gxa = (uint32_t)(g >> 1) << 4;
    const uint32_t gxb = (uint32_t)(g & 1) << 4;
    const uint32_t BQg = (uint32_t)nwarp * 8192u
                       + ((uint32_t)(g >> 1) << 11) + (uint32_t)l8 * 272;

    float b1v[8], b2v[8];
    int   i1v[8];
#pragma unroll
    for (int i = 0; i < 8; i++) { b1v[i] = -3.4e38f; b2v[i] = -3.4e38f; i1v[i] = 0; }

    for (int i = 0; i < count; i++) {
        const int u = start + i;
        const int stt = u / NT2;
        const int kc = u - stt * NT2;
        const int b = i & 1;

        if (stt != cur_st) {
            flush_fn(smem, cur_st, bid, b1v, i1v, b2v, tid, lane, mwarp, nwarp);
            buildA_hi(smem, x, stt * TM, tid);
            cur_st = stt;
#pragma unroll
            for (int s = 0; s < 8; s++) { b1v[s] = -3.4e38f; b2v[s] = -3.4e38f; i1v[s] = 0; }
        }

        if (i + 1 < count) {
            const int u2 = start + i + 1;
            stageB_hi(sb, tid, u2 - (u2 / NT2) * NT2, (i + 1) & 1);
            asm volatile("cp.async.wait_group 1;" ::: "memory");
        } else {
            asm volatile("cp.async.wait_group 0;" ::: "memory");
        }
        __syncthreads();

        const uint32_t Bt = sb + OFF_B + (uint32_t)b * BUFB + BQg;
        float acc[4][4][4];
#pragma unroll
        for (int ma = 0; ma < 4; ma++)
#pragma unroll
            for (int nn = 0; nn < 4; nn++)
#pragma unroll
                for (int r = 0; r < 4; r++) acc[ma][nn][r] = 0.f;

#pragma unroll
        for (int ks = 0; ks < 8; ks++) {
            const uint32_t kxa = ((uint32_t)ks << 5) | gxa;
            const uint32_t kxb = ((uint32_t)ks << 5) | gxb;
            uint32_t a[4][4];
            uint32_t bf[2][4];
#pragma unroll
            for (int ma = 0; ma < 4; ma++)
                LDSM4(a[ma], (AQ + (uint32_t)ma * 4096) ^ kxa);
#pragma unroll
            for (int nb = 0; nb < 2; nb++)
                LDSM4(bf[nb], (Bt + (uint32_t)nb * 4096) ^ kxb);
#pragma unroll
            for (int ma = 0; ma < 4; ma++)
#pragma unroll
                for (int nn = 0; nn < 4; nn++)
                    MMA(acc[ma][nn], a[ma],
                        bf[nn >> 1][2 * (nn & 1)], bf[nn >> 1][2 * (nn & 1) + 1]);
        }

        const float* hb = reinterpret_cast<const float*>(smem + OFF_H + b * 512);
        const int kbase = kc * KT + nwarp * 32 + (lane & 3) * 2;
#pragma unroll
        for (int ma = 0; ma < 4; ma++) {
            float c0[8], c1[8];
#pragma unroll
            for (int nn = 0; nn < 4; nn++) {
                int hi0 = nwarp * 32 + nn * 8 + (lane & 3) * 2;
                float h0 = hb[hi0], h1 = hb[hi0 + 1];
                c0[2 * nn]     = h0 - acc[ma][nn][0];
                c0[2 * nn + 1] = h1 - acc[ma][nn][1];
                c1[2 * nn]     = h0 - acc[ma][nn][2];
                c1[2 * nn + 1] = h1 - acc[ma][nn][3];
            }
#pragma unroll
            for (int rh = 0; rh < 2; rh++) {
                const float* cc = rh ? c1 : c0;
                const int s = 2 * ma + rh;
                float gm = cc[0];
#pragma unroll
                for (int q = 1; q < 8; q++) gm = fmaxf(gm, cc[q]);
                if (gm > b2v[s]) {
#pragma unroll
                    for (int q = 0; q < 8; q++) {
                        float d = cc[q];
                        int k = kbase + (q >> 1) * 8 + (q & 1);
                        if (d > b1v[s]) { b2v[s] = b1v[s]; b1v[s] = d; i1v[s] = k; }
                        else b2v[s] = fmaxf(b2v[s], d);
                    }
                }
            }
        }
        __syncthreads();
    }

    flush_fn(smem, cur_st, bid, b1v, i1v, b2v, tid, lane, mwarp, nwarp);
}

// ---------------------------------------------------------------------------
// decision with EXACT-ANCHOR certificate: merge top-2, compute exact fp32
// dist for candidate i1 (one warp-cooperative 128-dot), then certify with
//   exact(i1) - B2 > E   (error band only on the competitor side).
// Strictly more permissive than B1-B2 > 2E. grid = 2048 x 256.
// ---------------------------------------------------------------------------
__global__ void decision_kernel(const float* __restrict__ x) {
    const int lane = threadIdx.x & 31;
    const int n = blockIdx.x * 8 + (threadIdx.x >> 5);
    float4 xv = reinterpret_cast<const float4*>(x)[n * 32 + lane];
    float sh2 = 0.f, sr2 = 0.f;
    float vv[4] = {xv.x, xv.y, xv.z, xv.w};
#pragma unroll
    for (int j = 0; j < 4; j++) {
        float h = __half2float(__float2half_rn(vv[j]));
        float r = vv[j] - h;
        sh2 = fmaf(h, h, sh2);
        sr2 = fmaf(r, r, sr2);
    }
#pragma unroll
    for (int off = 16; off; off >>= 1) {
        sh2 += __shfl_xor_sync(0xffffffffu, sh2, off);
        sr2 += __shfl_xor_sync(0xffffffffu, sr2, off);
    }

    // lane 0 merges the CTA-slot top-2 records
    float B1 = 0.f, B2 = 0.f;
    int I1 = 0;
    if (lane == 0) {
        float4 t0 = g_top2[n * NSLOT + 0];
        B1 = t0.x; B2 = t0.y;
        I1 = __float_as_int(t0.z);
#pragma unroll
        for (int sl = 1; sl < NSLOT; sl++) {
            float4 tv = g_top2[n * NSLOT + sl];
            float c1 = tv.x, c2 = tv.y;
            int j1 = __float_as_int(tv.z);
            T2_MERGE(B1, I1, B2, c1, j1, c2);
        }
    }
    I1 = __shfl_sync(0xffffffffu, I1, 0);

    // warp-cooperative exact fp32 dot x . m_{I1}
    float4 cv = *reinterpret_cast<const float4*>(
        g_cmT + (size_t)I1 * DD + lane * 4);
    float dp = 0.f;
    dp = fmaf(xv.x, cv.x, dp);
    dp = fmaf(xv.y, cv.y, dp);
    dp = fmaf(xv.z, cv.z, dp);
    dp = fmaf(xv.w, cv.w, dp);
#pragma unroll
    for (int off = 16; off; off >>= 1)
        dp += __shfl_xor_sync(0xffffffffu, dp, off);

    if (lane == 0) {
        float Hbm = __uint_as_float(g_maxHb);
        float Rbm = __uint_as_float(g_maxRb);
        float nh = sqrtf(sh2), nr = sqrtf(sr2);
        // E covers |true(k) - approx(k)| for all k, plus fp32 eval slack for
        // both the MMA accumulations and the exact anchor dot (6e-3 total).
        float E = (nh * Rbm + nr * Hbm + nr * Rbm) * 1.001f + 6e-3f;
        float exact1 = g_h[I1] - dp;

        if (exact1 - B2 > E) {
            g_idx[n] = I1;
        } else {
            g_idx[n] = -1;
            g_bestu64[n] = 0ull;
            int p = atomicAdd(&g_fcount, 1);
            g_flist[p] = n;
        }
    }
}

// ---------------------------------------------------------------------------
// fallback2: 3-product MMA rescan of flagged samples (gathered A tiles).
// Persistent GRID CTAs over ceil(fcount/128) x 79 units. atomicMax publish.
// (byte-identical to the proven round-9 kernel)
// ---------------------------------------------------------------------------
__global__ void __launch_bounds__(256, 1)
fallback2_kernel(const float* __restrict__ x) {
    extern __shared__ __align__(1024) char smem[];
    const uint32_t sb = smem_u32(smem);
    const int tid = threadIdx.x;
    const int wid = tid >> 5;
    const int lane = tid & 31;
    const int l8 = lane & 7;
    const int gg = lane >> 3;
    const int mwarp = wid >> 2;
    const int nwarp = wid & 3;

    const int fcount = g_fcount;
    if (fcount == 0) return;
    const int nG = (fcount + 127) >> 7;
    const int total = nG * NT2;

    int* sids = reinterpret_cast<int*>(smem + F2_OFF_S);

    const uint32_t AQ  = sb + F2_OFF_A + (uint32_t)mwarp * 16384u
                       + (uint32_t)l8 * 272 + ((uint32_t)(gg & 1) << 11);
    const uint32_t gxa = (uint32_t)(gg >> 1) << 4;
    const uint32_t gxb = (uint32_t)(gg & 1) << 4;
    const uint32_t BQg = sb + F2_OFF_B + (uint32_t)nwarp * 8192u
                       + ((uint32_t)(gg >> 1) << 11) + (uint32_t)l8 * 272;

    for (int u = blockIdx.x; u < total; u += GRID) {
        const int gi = u / NT2;
        const int kt = u - gi * NT2;
        __syncthreads();

        if (tid < 128) {
            int fi = gi * 128 + tid;
            sids[tid] = (fi < fcount) ? g_flist[fi] : -1;
        }
        {
            const uint4* src = g_B4 + (size_t)kt * 4096;
#pragma unroll
            for (int i = 0; i < 16; i++)
                cp16(sb + F2_OFF_B + (uint32_t)(tid + i * 256) * 16,
                     src + tid + i * 256);
            if (tid < 32)
                cp16(sb + F2_OFF_H + (uint32_t)tid * 16,
                     (const char*)g_h + (size_t)kt * 512 + (size_t)tid * 16);
            CP_COMMIT();
        }
        __syncthreads();

        {
            const int row = tid >> 1;
            const int c0 = (tid & 1) * 8;
            const int n = sids[row];
            uint4* As = reinterpret_cast<uint4*>(smem + F2_OFF_A);
            if (n >= 0) {
                const float4* xr =
                    reinterpret_cast<const float4*>(x + (size_t)n * DD);
#pragma unroll
                for (int c = 0; c < 8; c++) {
                    float4 p = xr[(c0 + c) * 2];
                    float4 q = xr[(c0 + c) * 2 + 1];
                    float v[8] = {p.x, p.y, p.z, p.w, q.x, q.y, q.z, q.w};
                    uint4 H, M;
                    uint32_t* hp = &H.x; uint32_t* mp = &M.x;
#pragma unroll
                    for (int j = 0; j < 4; j++) {
                        float v0 = v[2 * j], v1 = v[2 * j + 1];
                        __half h0 = __float2half_rn(v0);
                        __half h1 = __float2half_rn(v1);
                        float r0 = v0 - __half2float(h0);
                        float r1 = v1 - __half2float(h1);
                        hp[j] = pk2h(v0, v1);
                        mp[j] = pk2h(r0, r1);
                    }
                    int ci = row * 16 + ((c0 + c) ^ (row & 7));
                    As[ci] = H;
                    As[ci + 2048] = M;
                }
            } else {
                uint4 Z = make_uint4(0, 0, 0, 0);
#pragma unroll
                for (int c = 0; c < 8; c++) {
                    int ci = row * 16 + ((c0 + c) ^ (row & 7));
                    As[ci] = Z;
                    As[ci + 2048] = Z;
                }
            }
        }
        asm volatile("cp.async.wait_group 0;" ::: "memory");
        __syncthreads();

        float acc[4][4][4];
#pragma unroll
        for (int ma = 0; ma < 4; ma++)
#pragma unroll
            for (int nn = 0; nn < 4; nn++)
#pragma unroll
                for (int r = 0; r < 4; r++) acc[ma][nn][r] = 0.f;

#pragma unroll
        for (int ks = 0; ks < 8; ks++) {
            const uint32_t kxa = ((uint32_t)ks << 5) | gxa;
            const uint32_t kxb = ((uint32_t)ks << 5) | gxb;
            uint32_t a[2][4][4];
            uint32_t bf[2][2][4];
#pragma unroll
            for (int s = 0; s < 2; s++)
#pragma unroll
                for (int ma = 0; ma < 4; ma++)
                    LDSM4(a[s][ma],
                          (AQ + (uint32_t)s * 32768 + (uint32_t)ma * 4096) ^ kxa);
#pragma unroll
            for (int s = 0; s < 2; s++)
#pragma unroll
                for (int nb = 0; nb < 2; nb++)
                    LDSM4(bf[s][nb],
                          (BQg + (uint32_t)s * 32768 + (uint32_t)nb * 4096) ^ kxb);

            const int PA[3] = {0, 0, 1};
            const int PB[3] = {0, 1, 0};
#pragma unroll
            for (int p = 0; p < 3; p++)
#pragma unroll
                for (int ma = 0; ma < 4; ma++)
#pragma unroll
                    for (int nn = 0; nn < 4; nn++)
                        MMA(acc[ma][nn], a[PA[p]][ma],
                            bf[PB[p]][nn >> 1][2 * (nn & 1)],
                            bf[PB[p]][nn >> 1][2 * (nn & 1) + 1]);
        }

        const float* hb = reinterpret_cast<const float*>(smem + F2_OFF_H);
        float* sbv = reinterpret_cast<float*>(smem + F2_OFF_A);
        int*   siv = reinterpret_cast<int*>(smem + F2_OFF_A + 2048);
        __syncthreads();
#pragma unroll
        for (int ma = 0; ma < 4; ma++)
#pragma unroll
            for (int rh = 0; rh < 2; rh++) {
                float bv = -3.4e38f;
                int bix = 0;
#pragma unroll
                for (int nn = 0; nn < 4; nn++) {
                    int hi0 = nwarp * 32 + nn * 8 + (lane & 3) * 2;
                    float d0 = hb[hi0] - acc[ma][nn][2 * rh];
                    float d1 = hb[hi0 + 1] - acc[ma][nn][2 * rh + 1];
                    int k0 = kt * KT + hi0;
                    if (d0 > bv) { bv = d0; bix = k0; }
                    if (d1 > bv) { bv = d1; bix = k0 + 1; }
                }
#pragma unroll
                for (int off = 1; off < 4; off <<= 1) {
                    float ov = __shfl_xor_sync(0xffffffffu, bv, off);
                    int   oi = __shfl_xor_sync(0xffffffffu, bix, off);
                    if (ov > bv || (ov == bv && oi < bix)) { bv = ov; bix = oi; }
                }
                if ((lane & 3) == 0) {
                    int row = mwarp * 64 + ma * 16 + rh * 8 + (lane >> 2);
                    sbv[row * 4 + nwarp] = bv;
                    siv[row * 4 + nwarp] = bix;
                }
            }
        __syncthreads();
        if (tid < 128) {
            float bv = sbv[tid * 4];
            int bix = siv[tid * 4];
#pragma unroll
            for (int w = 1; w < 4; w++) {
                float v = sbv[tid * 4 + w];
                int ix = siv[tid * 4 + w];
                if (v > bv || (v == bv && ix < bix)) { bv = v; bix = ix; }
            }
            int sid = sids[tid];
            if (sid >= 0) {
                unsigned long long key =
                    ((unsigned long long)enc_f(bv) << 32)
                    | (unsigned long long)(0xFFFFFFFFu - (unsigned)bix);
                atomicMax(&g_bestu64[sid], key);
            }
        }
    }
}

// ---------------------------------------------------------------------------
// gather quantize + index output + MSE (last block folds final reduction)
// ---------------------------------------------------------------------------
__global__ void gather_kernel(const float* __restrict__ x,
                              float* __restrict__ out) {
    __shared__ float red[256];
    __shared__ bool last;
    const int tid = threadIdx.x;
    float* out_q = out;
    float* out_idx_f = out + (size_t)NS * DD;

    int gt = blockIdx.x * 256 + tid;
    if (gt < NS) {
        int ix = g_idx[gt];
        if (ix < 0)
            ix = (int)(0xFFFFFFFFu - (unsigned)(g_bestu64[gt] & 0xFFFFFFFFull));
        out_idx_f[gt] = (float)ix;
    }

    float local = 0.f;
    for (int e4 = blockIdx.x * 256 + tid; e4 < NS * DD / 4;
         e4 += gridDim.x * 256) {
        int n = e4 >> 5;
        int d4 = (e4 & 31) * 4;
        int ix = g_idx[n];
        if (ix < 0)
            ix = (int)(0xFFFFFFFFu - (unsigned)(g_bestu64[n] & 0xFFFFFFFFull));
        float4 q = *reinterpret_cast<const float4*>(g_cmT + (size_t)ix * DD + d4);
        float4 xv = reinterpret_cast<const float4*>(x)[e4];
        reinterpret_cast<float4*>(out_q)[e4] = q;
        float a = xv.x - q.x, b = xv.y - q.y, c = xv.z - q.z, d = xv.w - q.w;
        local = fmaf(a, a, local);
        local = fmaf(b, b, local);
        local = fmaf(c, c, local);
        local = fmaf(d, d, local);
    }
    red[tid] = local;
    __syncthreads();
    for (int s = 128; s; s >>= 1) {
        if (tid < s) red[tid] += red[tid + s];
        __syncthreads();
    }
    if (tid == 0) {
        g_partial[blockIdx.x] = red[0];
        __threadfence();
        unsigned t = atomicAdd(&g_done, 1u);
        last = (t == gridDim.x - 1);
    }
    __syncthreads();
    if (last) {
        __threadfence();
        volatile float* gp = g_partial;
        __shared__ double dred[256];
        double acc = 0.0;
        for (int i = tid; i < 1024; i += 256) acc += (double)gp[i];
        dred[tid] = acc;
        __syncthreads();
        for (int st = 128; st; st >>= 1) {
            if (tid < st) dred[tid] += dred[tid + st];
            __syncthreads();
        }
        if (tid == 0)
            out[(size_t)NS * DD + NS] =
                (float)(dred[0] / (double)((size_t)NS * DD));
    }
}

// ---------------------------------------------------------------------------
extern "C" void kernel_launch(void* const* d_in, const int* in_sizes, int n_in,
                              void* d_out, int out_size) {
    const float* x  = (const float*)d_in[0];   // [16384, 128]
    const float* cm = (const float*)d_in[1];   // [128, 10000]
    float* out = (float*)d_out;                // [quantize | index | diff]

    cudaFuncSetAttribute(vq_main,
                         cudaFuncAttributeMaxDynamicSharedMemorySize, SMEM_TOTAL);
    cudaFuncSetAttribute(fallback2_kernel,
                         cudaFuncAttributeMaxDynamicSharedMemorySize, F2_SMEM);

    prepB_kernel<<<NT2 * 4, 256>>>(cm);
    vq_main<<<GRID2, 256, SMEM_TOTAL>>>(x);
    decision_kernel<<<NS / 8, 256>>>(x);
    fallback2_kernel<<<GRID, 256, F2_SMEM>>>(x);
    gather_kernel<<<1024, 256>>>(x, out);
}